// round 2
// baseline (speedup 1.0000x reference)
#include <cuda_runtime.h>
#include <math.h>

// ---------------- problem constants ----------------
#define Lq   4          // sequence length (B=1)
#define Cc   128        // channels
#define Ch   64         // hidden = C/2
#define Rr   8          // rank
#define Kk   36         // Lmax^2
#define HW   115200     // 240*480 pixels per plane
#define WFN  (Cc*Rr + Rr*Kk)   // 1312 hypernet output width

// ---------------- device scratch (no allocations allowed) ----------------
__device__ float g_ctx[Lq * Cc];          // pooled means  (4*128)
__device__ float g_gW1[Lq * Cc * Rr];     // gain[c] * W1[l,c,r]   (4*1024)
__device__ float g_W2 [Lq * Rr * Kk];     // W2[l,r,k]             (4*288)

// ============================================================
// Kernel 1: per-(l,c) plane mean of x  -> g_ctx
// grid = 512 blocks (one per plane), 256 threads
// ============================================================
__global__ void mean_kernel(const float* __restrict__ x)
{
    const int plane = blockIdx.x;                 // l*128 + c
    const float4* __restrict__ p = (const float4*)(x + (size_t)plane * HW);
    const int n4 = HW / 4;                        // 28800

    float s = 0.f;
    for (int i = threadIdx.x; i < n4; i += blockDim.x) {
        float4 v = p[i];
        s += (v.x + v.y) + (v.z + v.w);
    }
    // warp reduce
    #pragma unroll
    for (int o = 16; o > 0; o >>= 1)
        s += __shfl_xor_sync(0xffffffffu, s, o);

    __shared__ float ws[8];
    const int lane = threadIdx.x & 31, wid = threadIdx.x >> 5;
    if (lane == 0) ws[wid] = s;
    __syncthreads();
    if (wid == 0) {
        s = (lane < (blockDim.x >> 5)) ? ws[lane] : 0.f;
        #pragma unroll
        for (int o = 4; o > 0; o >>= 1)
            s += __shfl_xor_sync(0xffffffffu, s, o);
        if (lane == 0)
            g_ctx[plane] = s * (1.0f / (float)HW);
    }
}

// ============================================================
// Kernel 2: hypernet (tiny).  1 block, 512 threads.
//   h = silu(ctx @ Wa + ba)            (4 x 64)
//   wf = h @ Wb + bb                   (4 x 1312)
//   gW1[l,c,r] = gain[c] * wf[l, c*8+r]
//   W2 [l,r,k] =           wf[l, 1024 + r*36+k]
// ============================================================
__global__ void hyper_kernel(const float* __restrict__ Wa,
                             const float* __restrict__ ba,
                             const float* __restrict__ Wb,
                             const float* __restrict__ bb,
                             const float* __restrict__ gain)
{
    __shared__ float hs[Lq * Ch];          // 256 floats
    __shared__ float ctxs[Lq * Cc];        // 512 floats

    const int tid = threadIdx.x;
    // stage ctx into smem
    if (tid < Lq * Cc) ctxs[tid] = g_ctx[tid];
    __syncthreads();

    // phase A: h[l][j], 256 outputs
    if (tid < Lq * Ch) {
        const int l = tid >> 6;            // /64
        const int j = tid & 63;
        float acc = ba[j];
        const float* c = &ctxs[l * Cc];
        #pragma unroll 8
        for (int i = 0; i < Cc; i++)
            acc = fmaf(c[i], Wa[i * Ch + j], acc);
        // silu
        hs[tid] = acc / (1.0f + expf(-acc));
    }
    __syncthreads();

    // phase B: wf outputs, 4*1312 = 5248
    for (int idx = tid; idx < Lq * WFN; idx += blockDim.x) {
        const int l   = idx / WFN;
        const int col = idx - l * WFN;
        float acc = bb[col];
        const float* h = &hs[l * Ch];
        #pragma unroll 8
        for (int j = 0; j < Ch; j++)
            acc = fmaf(h[j], Wb[j * WFN + col], acc);
        if (col < Cc * Rr) {
            const int c = col >> 3;        // col / R
            g_gW1[l * (Cc * Rr) + col] = gain[c] * acc;
        } else {
            g_W2[l * (Rr * Kk) + (col - Cc * Rr)] = acc;
        }
    }
}

// ============================================================
// Kernel 3: fused  z = W2 @ Y  (per pixel)  +  out = x + W1g @ z
// grid = (225, 4), 128 threads, 4 pixels/thread (float4).
// 115200 = 225 * 128 * 4
// ============================================================
__global__ void __launch_bounds__(128)
bias_kernel(const float* __restrict__ x,
            const float* __restrict__ Y,
            float*       __restrict__ out)
{
    const int l  = blockIdx.y;
    const int p0 = (blockIdx.x * 128 + threadIdx.x) * 4;

    __shared__ float sW2[Rr * Kk];         // 288
    __shared__ float sW1[Cc * Rr];         // 1024

    for (int i = threadIdx.x; i < Rr * Kk; i += 128) sW2[i] = g_W2[l * Rr * Kk + i];
    for (int i = threadIdx.x; i < Cc * Rr; i += 128) sW1[i] = g_gW1[l * Cc * Rr + i];
    __syncthreads();

    // ---- z[r] for 4 pixels ----
    float4 z[Rr];
    #pragma unroll
    for (int r = 0; r < Rr; r++) z[r] = make_float4(0.f, 0.f, 0.f, 0.f);

    #pragma unroll
    for (int k = 0; k < Kk; k++) {
        const float4 y = *(const float4*)(Y + (size_t)k * HW + p0);
        #pragma unroll
        for (int r = 0; r < Rr; r++) {
            const float w = sW2[r * Kk + k];
            z[r].x = fmaf(w, y.x, z[r].x);
            z[r].y = fmaf(w, y.y, z[r].y);
            z[r].z = fmaf(w, y.z, z[r].z);
            z[r].w = fmaf(w, y.w, z[r].w);
        }
    }

    // ---- out = x + gW1 . z over 128 channels ----
    const float* xb = x   + (size_t)l * Cc * HW + p0;
    float*       ob = out + (size_t)l * Cc * HW + p0;

    #pragma unroll 4
    for (int c = 0; c < Cc; c++) {
        float4 v = *(const float4*)(xb + (size_t)c * HW);
        const float4 wa = *(const float4*)&sW1[c * Rr];
        const float4 wb = *(const float4*)&sW1[c * Rr + 4];

        v.x = fmaf(wa.x, z[0].x, v.x); v.y = fmaf(wa.x, z[0].y, v.y);
        v.z = fmaf(wa.x, z[0].z, v.z); v.w = fmaf(wa.x, z[0].w, v.w);
        v.x = fmaf(wa.y, z[1].x, v.x); v.y = fmaf(wa.y, z[1].y, v.y);
        v.z = fmaf(wa.y, z[1].z, v.z); v.w = fmaf(wa.y, z[1].w, v.w);
        v.x = fmaf(wa.z, z[2].x, v.x); v.y = fmaf(wa.z, z[2].y, v.y);
        v.z = fmaf(wa.z, z[2].z, v.z); v.w = fmaf(wa.z, z[2].w, v.w);
        v.x = fmaf(wa.w, z[3].x, v.x); v.y = fmaf(wa.w, z[3].y, v.y);
        v.z = fmaf(wa.w, z[3].z, v.z); v.w = fmaf(wa.w, z[3].w, v.w);
        v.x = fmaf(wb.x, z[4].x, v.x); v.y = fmaf(wb.x, z[4].y, v.y);
        v.z = fmaf(wb.x, z[4].z, v.z); v.w = fmaf(wb.x, z[4].w, v.w);
        v.x = fmaf(wb.y, z[5].x, v.x); v.y = fmaf(wb.y, z[5].y, v.y);
        v.z = fmaf(wb.y, z[5].z, v.z); v.w = fmaf(wb.y, z[5].w, v.w);
        v.x = fmaf(wb.z, z[6].x, v.x); v.y = fmaf(wb.z, z[6].y, v.y);
        v.z = fmaf(wb.z, z[6].z, v.z); v.w = fmaf(wb.z, z[6].w, v.w);
        v.x = fmaf(wb.w, z[7].x, v.x); v.y = fmaf(wb.w, z[7].y, v.y);
        v.z = fmaf(wb.w, z[7].z, v.z); v.w = fmaf(wb.w, z[7].w, v.w);

        *(float4*)(ob + (size_t)c * HW) = v;
    }
}

// ============================================================
extern "C" void kernel_launch(void* const* d_in, const int* in_sizes, int n_in,
                              void* d_out, int out_size)
{
    const float* x    = (const float*)d_in[0];
    const float* Wa   = (const float*)d_in[1];
    const float* ba   = (const float*)d_in[2];
    const float* Wb   = (const float*)d_in[3];
    const float* bb   = (const float*)d_in[4];
    const float* gain = (const float*)d_in[5];
    const float* Y    = (const float*)d_in[6];
    float* out        = (float*)d_out;

    mean_kernel<<<Lq * Cc, 256>>>(x);
    hyper_kernel<<<1, 512>>>(Wa, ba, Wb, bb, gain);
    bias_kernel<<<dim3(225, Lq), 128>>>(x, Y, out);
}